// round 9
// baseline (speedup 1.0000x reference)
#include <cuda_runtime.h>
#include <math.h>

#define IMG   512
#define NVIEW 180
#define NPIX  (IMG * IMG)

typedef unsigned long long ull;

// Interleaved copy of both batch images: g_xi[y*512+x] = (batch0, batch1).
__device__ float2 g_xi[NPIX];

struct Params {
    float2 cs[NVIEW];            // (cos, sin) per view, fp32 from double (matches numpy)
    unsigned char lw[NVIEW];     // tile shape per view
    unsigned short order[NVIEW]; // views sorted by descending cost (for pairing)
};

// ---- packed f32x2 helpers (sm_100+) ----
__device__ __forceinline__ ull pk(float lo, float hi) {
    ull r; asm("mov.b64 %0,{%1,%2};" : "=l"(r) : "f"(lo), "f"(hi)); return r;
}
__device__ __forceinline__ void upk(ull p, float& lo, float& hi) {
    asm("mov.b64 {%0,%1},%2;" : "=f"(lo), "=f"(hi) : "l"(p));
}
__device__ __forceinline__ ull mul2(ull a, ull b) {
    ull r; asm("mul.rn.f32x2 %0,%1,%2;" : "=l"(r) : "l"(a), "l"(b)); return r;
}
__device__ __forceinline__ ull add2(ull a, ull b) {
    ull r; asm("add.rn.f32x2 %0,%1,%2;" : "=l"(r) : "l"(a), "l"(b)); return r;
}
__device__ __forceinline__ ull fma2(ull a, ull b, ull c) {
    ull r; asm("fma.rn.f32x2 %0,%1,%2,%3;" : "=l"(r) : "l"(a), "l"(b), "l"(c)); return r;
}

// Interleave prep (4 pixels/thread, 128-bit ld/st) + zero the output buffer
// (required: radon blocks accumulate partial sums with atomicAdd).
__global__ __launch_bounds__(256) void prep_kernel(const float* __restrict__ x,
                                                   float* __restrict__ out) {
    int i = blockIdx.x * blockDim.x + threadIdx.x;           // 65536 threads
    const float4* a4 = (const float4*)x;                      // batch 0
    const float4* b4 = (const float4*)(x + NPIX);             // batch 1
    float4 a = a4[i];
    float4 b = b4[i];
    float4* o = (float4*)&g_xi[i * 4];
    o[0] = make_float4(a.x, b.x, a.y, b.y);
    o[1] = make_float4(a.z, b.z, a.w, b.w);
    if (i < (2 * NVIEW * IMG) / 4) {                          // 184320 floats
        ((float4*)out)[i] = make_float4(0.f, 0.f, 0.f, 0.f);
    }
}

// Warp tile: W lanes along w, H = 32/W lanes along h; warp makes 16 outputs
// (NC chunks). Outer iteration 'to' covers rows [8*to, 8*to+8); this body
// handles to in [lo, hi_) (one half of the view), clipped further by the
// conservative valid window (skip only if ALL lanes certainly invalid:
// s>=0 on [0,pi) and the -1 clamp maps to valid index 0, so invalid only
// when gx>1 or gy>1; both are monotone in h). Partial sums are combined
// across the two halves with atomicAdd (2 commutative adds into a zeroed
// cell -> deterministic).
template<int LOGW>
__device__ __forceinline__ void radon_body(float* __restrict__ out, int v, float2 cs,
                                           int lo, int hi_) {
    constexpr int W  = 1 << LOGW;
    constexpr int H  = 32 >> LOGW;
    constexpr int NC = 16 / W;     // w-chunks per warp
    constexpr int G  = W / 4;      // h-steps per outer iter (G*NC == 4)

    const int lane = threadIdx.x & 31;
    const int warp = threadIdx.x >> 5;
    const int wi   = lane & (W - 1);
    const int hi   = lane >> LOGW;
    const int wbase = ((blockIdx.x & 7) << 6) + (warp << 4);

    const float c = cs.x, s = cs.y;
    const ull csP  = pk(s, c);          // (s, c)
    const ull sgnP = pk(-1.0f, 1.0f);   // gx = P - s*gy0 ; gy = S + c*gy0

    ull PS[NC], acc[NC];
    #pragma unroll
    for (int j = 0; j < NC; j++) {
        int w = wbase + j * W + wi;
        float gx0 = __fmaf_rn((float)w, 1.0f / 256.0f, -511.0f / 512.0f);  // exact
        PS[j] = pk(__fmul_rn(c, gx0), __fmul_rn(s, gx0));   // (P, S)
        acc[j] = 0ull;
    }

    // ---- conservative per-warp valid window over outer iterations ----
    int to_s = lo, to_e = hi_;
    {
        float gx0a = __fmaf_rn((float)wbase,        1.0f / 256.0f, -511.0f / 512.0f);
        float gx0b = __fmaf_rn((float)(wbase + 15), 1.0f / 256.0f, -511.0f / 512.0f);
        float m1 = fminf(c * gx0a, c * gx0b);   // min over lanes of c*gx0
        float M2 = fminf(s * gx0a, s * gx0b);   // min over lanes of s*gx0
        if (s > 1e-6f && m1 > 1.0f) {           // all-gx-invalid for to < T
            float T = (256.0f * (m1 - 1.0f) / s + 248.5f) * 0.125f;
            int t = (int)floorf(T) - 1;
            if (t > to_s) to_s = t;
        }
        if (c < -1e-6f) {                       // c<0: gy decreasing in h
            float T = (256.0f * (1.0f - M2) / c + 248.5f) * 0.125f;
            int t = (int)floorf(T) - 1;
            if (t > to_s) to_s = t;
        } else if (c > 1e-6f) {                 // c>0: gy increasing in h
            float T = (256.0f * (1.0f - M2) / c + 255.5f) * 0.125f;
            int t = (int)ceilf(T) + 2;
            if (t < to_e) to_e = t;
        }
        if (to_s < lo) to_s = lo;
        if (to_e > hi_) to_e = hi_;
        if (to_e < to_s) to_e = to_s;
    }

    // gy0 starts at h = hi + 8*to_s; all values and increments exact in fp32
    float gy0 = __fmaf_rn((float)(hi + 8 * to_s), 1.0f / 256.0f, -511.0f / 512.0f);
    ull gy0p = pk(gy0, gy0);
    const ull stepP = pk((float)H / 256.0f, (float)H / 256.0f);

    const float MAGIC = 12582912.0f;      // 1.5*2^23: magic round-half-even
    const float BOUND = 12583424.0f;      // MAGIC + 512
    const ull ONE2 = pk(1.0f, 1.0f);
    const ull C256 = pk(256.0f, 256.0f);
    const ull MH2  = pk(-0.5f, -0.5f);
    const ull MAG2 = pk(MAGIC, MAGIC);

    #pragma unroll 1
    for (int to = to_s; to < to_e; to++) {
        #pragma unroll
        for (int g = 0; g < G; g++) {
            ull qp = mul2(gy0p, csP);         // (s*gy0, c*gy0), each rounded once
            gy0p = add2(gy0p, stepP);         // exact
            #pragma unroll
            for (int j = 0; j < NC; j++) {
                ull gp = fma2(qp, sgnP, PS[j]);   // (fl(P - s*gy0), fl(S + c*gy0))
                ull up = add2(gp, ONE2);          // fl(clamp(g,-1)+1) == fmax(fl(g+1),0)
                float ux, uy; upk(up, ux, uy);
                ux = fmaxf(ux, 0.0f);
                uy = fmaxf(uy, 0.0f);
                // ((g+1)*512-1)*0.5 == fma(u,256,-0.5) exactly; +MAGIC = rint(ties-even)
                ull rp = add2(fma2(pk(ux, uy), C256, MH2), MAG2);
                float rx, ry; upk(rp, rx, ry);
                bool ok = fmaxf(rx, ry) < BOUND;  // ix,iy >= 0 guaranteed by clamp
                unsigned idx = (unsigned)__float_as_int(ry) * 512u
                             + (unsigned)__float_as_int(rx)
                             - 0x4B400000u * 513u;
                ull val = 0ull;
                if (ok) val = __ldg((const ull*)((const char*)g_xi + (size_t)idx * 8u));
                acc[j] = add2(acc[j], val);
            }
        }
    }

    // reduce over the H h-lanes of each chunk, then accumulate into out
    #pragma unroll
    for (int j = 0; j < NC; j++) {
        float a0, a1; upk(acc[j], a0, a1);
        #pragma unroll
        for (int off = W; off < 32; off <<= 1) {
            a0 += __shfl_xor_sync(0xffffffffu, a0, off);
            a1 += __shfl_xor_sync(0xffffffffu, a1, off);
        }
        if (hi == 0) {
            int w = wbase + j * W + wi;
            atomicAdd(&out[v * IMG + w],               a0 * (1.0f / 512.0f));
            atomicAdd(&out[NVIEW * IMG + v * IMG + w], a1 * (1.0f / 512.0f));
        }
    }
}

__device__ __forceinline__ void dispatch(float* out, const Params& p, int v,
                                         int lo, int hi_) {
    float2 cs = p.cs[v];
    switch (p.lw[v]) {
        case 2: radon_body<2>(out, v, cs, lo, hi_); break;
        case 3: radon_body<3>(out, v, cs, lo, hi_); break;
        default: radon_body<4>(out, v, cs, lo, hi_); break;
    }
}

// Cost-paired blocks: grid (16, 90). Pair p couples hard view order[p] with
// easy view order[179-p]. bx = (wblock 0..7) | (half << 3). Each block does
// half the h-range of the hard view + the other half of the easy view ->
// near-uniform block durations -> flat wave drain. 1440 blocks <= 1480 slots.
__global__ __launch_bounds__(128, 10) void radon_kernel(float* __restrict__ out, Params p) {
    const int pair = blockIdx.y;
    const int half = (blockIdx.x >> 3) & 1;
    const int va = p.order[pair];
    const int vb = p.order[NVIEW - 1 - pair];
    dispatch(out, p, va, 32 * half, 32 * half + 32);
    dispatch(out, p, vb, 32 * (half ^ 1), 32 * (half ^ 1) + 32);
}

extern "C" void kernel_launch(void* const* d_in, const int* in_sizes, int n_in,
                              void* d_out, int out_size) {
    const float* x = (const float*)d_in[0];
    float* out = (float*)d_out;

    prep_kernel<<<NPIX / 4 / 256, 256>>>(x, out);

    // Host-side trig (exactly numpy's fp32 cast), tile shapes, cost ordering.
    static Params p;
    static double cost[NVIEW];
    for (int v = 0; v < NVIEW; v++) {
        double th = (double)v * (M_PI / 180.0);
        p.cs[v] = make_float2((float)cos(th), (float)sin(th));
        double ac = fabs(cos(th)), as = fabs(sin(th));
        int best = 2; double bestcost = 1e30;
        for (int lw = 2; lw <= 4; lw++) {
            double W = (double)(1 << lw), H = 32.0 / W;
            double rows = W * as + H * ac + 1.0;
            double segB = (W * ac + H * as) * 8.0 + 8.0;
            double cc = rows * (1.0 + segB / 128.0);
            if (cc < bestcost) { bestcost = cc; best = lw; }
        }
        p.lw[v] = (unsigned char)best;
        cost[v] = bestcost;
        p.order[v] = (unsigned short)v;
    }
    // insertion sort by descending cost (perf-only; any order is correct)
    for (int i = 1; i < NVIEW; i++) {
        unsigned short key = p.order[i];
        int j = i - 1;
        while (j >= 0 && cost[p.order[j]] < cost[key]) { p.order[j + 1] = p.order[j]; j--; }
        p.order[j + 1] = key;
    }

    dim3 grid(16, NVIEW / 2);
    radon_kernel<<<grid, 128>>>(out, p);
}